// round 6
// baseline (speedup 1.0000x reference)
#include <cuda_runtime.h>
#include <cuda_bf16.h>
#include <math.h>
#include <stdint.h>

// Problem shape constants
#define BB 8
#define LL 512
#define NN 2048
#define CC 1024
#define DD 128

// ---------------------------------------------------------------------------
// Scratch (device globals — no allocations allowed)
// ---------------------------------------------------------------------------
__device__ __align__(16) __nv_bfloat16 g_feat_h[BB * NN * CC];   // 32 MB
__device__ __align__(16) __nv_bfloat16 g_feat_l[BB * NN * CC];
__device__ __align__(16) __nv_bfloat16 g_log_h[BB * LL * NN];    // 16 MB
__device__ __align__(16) __nv_bfloat16 g_log_l[BB * LL * NN];
__device__ __align__(16) __nv_bfloat16 g_wq_h[DD * CC];
__device__ __align__(16) __nv_bfloat16 g_wq_l[DD * CC];
__device__ __align__(16) __nv_bfloat16 g_wk_h[DD * CC];
__device__ __align__(16) __nv_bfloat16 g_wk_l[DD * CC];
__device__ __align__(16) __nv_bfloat16 g_q_h[BB * NN * DD];      // 4 MB
__device__ __align__(16) __nv_bfloat16 g_q_l[BB * NN * DD];
__device__ __align__(16) __nv_bfloat16 g_k_h[BB * NN * DD];
__device__ __align__(16) __nv_bfloat16 g_k_l[BB * NN * DD];
__device__ __align__(16) __nv_bfloat16 g_attn_h[(size_t)BB * NN * NN]; // 64 MB (unnormalized exp)
__device__ __align__(16) __nv_bfloat16 g_attn_l[(size_t)BB * NN * NN]; // 64 MB
__device__ __align__(16) float g_psum[BB * NN * 16];             // per-tile row sums
__device__ __align__(16) float g_invS[BB * NN];                  // 1/rowsum

// ---------------------------------------------------------------------------
// Helpers (family-portable PTX only: ldmatrix / mma.sync / cp.async)
// ---------------------------------------------------------------------------
__device__ __forceinline__ uint32_t smem_u32(const void* p) {
    uint32_t a;
    asm("{ .reg .u64 t; cvta.to.shared.u64 t, %1; cvt.u32.u64 %0, t; }"
        : "=r"(a) : "l"(p));
    return a;
}

__device__ __forceinline__ uint32_t sw128(uint32_t off) {
    return off ^ ((off >> 3) & 0x70);
}

__device__ __forceinline__ void ldm_x4(uint32_t r[4], uint32_t addr) {
    asm volatile("ldmatrix.sync.aligned.m8n8.x4.shared.b16 {%0,%1,%2,%3}, [%4];"
                 : "=r"(r[0]), "=r"(r[1]), "=r"(r[2]), "=r"(r[3])
                 : "r"(addr));
}

__device__ __forceinline__ void mma_bf16(float d[4], const uint32_t a[4],
                                         uint32_t b0, uint32_t b1) {
    asm volatile(
        "mma.sync.aligned.m16n8k16.row.col.f32.bf16.bf16.f32 "
        "{%0,%1,%2,%3}, {%4,%5,%6,%7}, {%8,%9}, {%0,%1,%2,%3};"
        : "+f"(d[0]), "+f"(d[1]), "+f"(d[2]), "+f"(d[3])
        : "r"(a[0]), "r"(a[1]), "r"(a[2]), "r"(a[3]), "r"(b0), "r"(b1));
}

__device__ __forceinline__ void cpa16(uint32_t dst, const void* src) {
    asm volatile("cp.async.cg.shared.global [%0], [%1], 16;"
                 :: "r"(dst), "l"(src));
}
__device__ __forceinline__ void cp_commit() {
    asm volatile("cp.async.commit_group;" ::: "memory");
}
__device__ __forceinline__ void cp_wait1() {
    asm volatile("cp.async.wait_group 1;" ::: "memory");
}
__device__ __forceinline__ void cp_wait0() {
    asm volatile("cp.async.wait_group 0;" ::: "memory");
}

// split fp32 -> (bf16 hi, bf16 lo) packed pairs
__device__ __forceinline__ void split2(float x0, float x1, uint32_t& hi, uint32_t& lo) {
    __nv_bfloat16 h0 = __float2bfloat16_rn(x0);
    __nv_bfloat16 h1 = __float2bfloat16_rn(x1);
    __nv_bfloat16 l0 = __float2bfloat16_rn(x0 - __bfloat162float(h0));
    __nv_bfloat16 l1 = __float2bfloat16_rn(x1 - __bfloat162float(h1));
    hi = ((uint32_t)__bfloat16_as_ushort(h1) << 16) | __bfloat16_as_ushort(h0);
    lo = ((uint32_t)__bfloat16_as_ushort(l1) << 16) | __bfloat16_as_ushort(l0);
}

// ---------------------------------------------------------------------------
// Elementwise split: fp32 -> hi/lo bf16 (4 elements / thread)
// ---------------------------------------------------------------------------
__global__ __launch_bounds__(256) void split_kernel(
    const float4* __restrict__ src, uint2* __restrict__ hi,
    uint2* __restrict__ lo, int n4)
{
    int i = blockIdx.x * 256 + threadIdx.x;
    if (i < n4) {
        float4 v = src[i];
        uint32_t h0, l0, h1, l1;
        split2(v.x, v.y, h0, l0);
        split2(v.z, v.w, h1, l1);
        hi[i] = make_uint2(h0, h1);
        lo[i] = make_uint2(l0, l1);
    }
}

// ---------------------------------------------------------------------------
// Row-sum reduce + invert: invS[r] = 1 / sum_t psum[r][t]
// ---------------------------------------------------------------------------
__global__ __launch_bounds__(256) void rowsum_inv_kernel(
    const float* __restrict__ psum, float* __restrict__ invS, int ntiles)
{
    const int r = blockIdx.x * 256 + threadIdx.x;
    float s = 0.0f;
    #pragma unroll
    for (int i = 0; i < 16; ++i) s += psum[(long long)r * ntiles + i];
    invS[r] = 1.0f / s;
}

// ---------------------------------------------------------------------------
// bf16 HMMA NT GEMM with 3-term split: C = Ah*Bh + Al*Bh + Ah*Bl
// CTA tile 128x128, K-chunk 64, 3-stage cp.async pipeline.
// Epilogue modes:
//   Cf != 0                : fp32 output (+bias), optionally * invS[col]
//   Ch != 0 && psum == 0   : bf16 hi/lo output (+bias)
//   Ch != 0 && psum != 0   : p = exp(acc); bf16 hi/lo output; per-tile row sums
// ---------------------------------------------------------------------------
#define NSTAGE 3
#define STAGE_BYTES 65536   // Ah 16K | Al 16K | Bh 16K | Bl 16K
#define GSMEM (NSTAGE * STAGE_BYTES)

__device__ __forceinline__ void fill_stage(uint32_t st,
    const __nv_bfloat16* __restrict__ ah, const __nv_bfloat16* __restrict__ al,
    const __nv_bfloat16* __restrict__ bh, const __nv_bfloat16* __restrict__ bl,
    int K, int tid)
{
    #pragma unroll
    for (int i = 0; i < 4; ++i) {
        const int id  = tid + (i << 8);
        const int row = id >> 3, g = id & 7;
        const long long goff = (long long)row * K + (g << 3);
        const uint32_t so = sw128((uint32_t)((row << 7) + (g << 4)));
        cpa16(st + so,          ah + goff);
        cpa16(st + 16384 + so,  al + goff);
        cpa16(st + 32768 + so,  bh + goff);
        cpa16(st + 49152 + so,  bl + goff);
    }
    cp_commit();
}

__global__ __launch_bounds__(256, 1) void hgemm_nt(
    const __nv_bfloat16* __restrict__ Ah, const __nv_bfloat16* __restrict__ Al,
    const __nv_bfloat16* __restrict__ Bh, const __nv_bfloat16* __restrict__ Bl,
    float* __restrict__ Cf,
    __nv_bfloat16* __restrict__ Ch, __nv_bfloat16* __restrict__ Cl,
    const float* __restrict__ bias,
    float* __restrict__ psum,          // per-tile row sums (exp mode)
    const float* __restrict__ invS,    // column scale (agg mode)
    int M, int N, int K,
    long long sA, long long sB, long long sC)
{
    extern __shared__ char smem[];
    const uint32_t sbase = smem_u32(smem);
    const int tid  = threadIdx.x;
    const int lane = tid & 31;
    const int wid  = tid >> 5;

    const int bz = blockIdx.z;
    const int m0 = blockIdx.y * 128;
    const int n0 = blockIdx.x * 128;

    const __nv_bfloat16* Aht = Ah + bz * sA + (long long)m0 * K;
    const __nv_bfloat16* Alt = Al + bz * sA + (long long)m0 * K;
    const __nv_bfloat16* Bht = Bh + bz * sB + (long long)n0 * K;
    const __nv_bfloat16* Blt = Bl + bz * sB + (long long)n0 * K;

    // warp tiling: 8 warps = 4(m) x 2(n); warp tile 32(m) x 64(n)
    const int wm = (wid & 3) * 32;
    const int wn = (wid >> 2) * 64;
    const int qq = lane >> 3;
    const int rr = lane & 7;

    float acc[2][8][4];
    #pragma unroll
    for (int mi = 0; mi < 2; mi++)
        #pragma unroll
        for (int ni = 0; ni < 8; ni++)
            #pragma unroll
            for (int c = 0; c < 4; c++) acc[mi][ni][c] = 0.0f;

    const int nch = K / 64;

    fill_stage(sbase, Aht, Alt, Bht, Blt, K, tid);
    if (nch > 1)
        fill_stage(sbase + STAGE_BYTES, Aht + 64, Alt + 64, Bht + 64, Blt + 64, K, tid);

    for (int it = 0; it < nch; ++it) {
        if (it + 1 < nch) cp_wait1(); else cp_wait0();
        __syncthreads();

        const uint32_t st = sbase + (uint32_t)(it % NSTAGE) * STAGE_BYTES;

        #pragma unroll
        for (int ks = 0; ks < 4; ++ks) {
            const int ko = ks * 16;
            uint32_t ah[2][4], al[2][4], bb[4][4];
            uint32_t aoff[2], boff[4];
            #pragma unroll
            for (int mi = 0; mi < 2; ++mi) {
                aoff[mi] = sw128((uint32_t)((wm + mi * 16 + rr + (qq & 1) * 8) * 128
                                            + (ko + (qq >> 1) * 8) * 2));
                ldm_x4(ah[mi], st + aoff[mi]);
                ldm_x4(al[mi], st + 16384 + aoff[mi]);
            }
            #pragma unroll
            for (int bi = 0; bi < 4; ++bi) {
                boff[bi] = sw128((uint32_t)((wn + bi * 16 + rr + (qq >> 1) * 8) * 128
                                            + (ko + (qq & 1) * 8) * 2));
                ldm_x4(bb[bi], st + 32768 + boff[bi]);
            }
            // hi*hi
            #pragma unroll
            for (int mi = 0; mi < 2; ++mi)
                #pragma unroll
                for (int ni = 0; ni < 8; ++ni)
                    mma_bf16(acc[mi][ni], ah[mi],
                             bb[ni >> 1][(ni & 1) * 2], bb[ni >> 1][(ni & 1) * 2 + 1]);
            // lo*hi
            #pragma unroll
            for (int mi = 0; mi < 2; ++mi)
                #pragma unroll
                for (int ni = 0; ni < 8; ++ni)
                    mma_bf16(acc[mi][ni], al[mi],
                             bb[ni >> 1][(ni & 1) * 2], bb[ni >> 1][(ni & 1) * 2 + 1]);
            // hi*lo (reload bb with B_lo)
            #pragma unroll
            for (int bi = 0; bi < 4; ++bi)
                ldm_x4(bb[bi], st + 49152 + boff[bi]);
            #pragma unroll
            for (int mi = 0; mi < 2; ++mi)
                #pragma unroll
                for (int ni = 0; ni < 8; ++ni)
                    mma_bf16(acc[mi][ni], ah[mi],
                             bb[ni >> 1][(ni & 1) * 2], bb[ni >> 1][(ni & 1) * 2 + 1]);
        }

        if (it + 2 < nch) {
            const int k0 = (it + 2) * 64;
            fill_stage(sbase + (uint32_t)((it + 2) % NSTAGE) * STAGE_BYTES,
                       Aht + k0, Alt + k0, Bht + k0, Blt + k0, K, tid);
        }
    }

    // ---------------- epilogue ----------------
    const int g  = lane >> 2;
    const int t4 = lane & 3;

    if (psum) {
        // exp + split-store + deterministic per-tile row sums
        float rsum[2][2] = {{0.0f, 0.0f}, {0.0f, 0.0f}};
        #pragma unroll
        for (int mi = 0; mi < 2; ++mi) {
            const int row = m0 + wm + mi * 16 + g;
            #pragma unroll
            for (int ni = 0; ni < 8; ++ni) {
                const int col = n0 + wn + ni * 8 + t4 * 2;
                const float e00 = __expf(acc[mi][ni][0]);
                const float e01 = __expf(acc[mi][ni][1]);
                const float e10 = __expf(acc[mi][ni][2]);
                const float e11 = __expf(acc[mi][ni][3]);
                rsum[mi][0] += e00 + e01;
                rsum[mi][1] += e10 + e11;
                uint32_t h, l;
                split2(e00, e01, h, l);
                *reinterpret_cast<uint32_t*>(&Ch[bz * sC + (long long)row * N + col]) = h;
                *reinterpret_cast<uint32_t*>(&Cl[bz * sC + (long long)row * N + col]) = l;
                split2(e10, e11, h, l);
                *reinterpret_cast<uint32_t*>(&Ch[bz * sC + (long long)(row + 8) * N + col]) = h;
                *reinterpret_cast<uint32_t*>(&Cl[bz * sC + (long long)(row + 8) * N + col]) = l;
            }
        }
        // reduce over t4 lanes (same g = 4 consecutive lanes)
        #pragma unroll
        for (int o = 1; o <= 2; o <<= 1) {
            #pragma unroll
            for (int mi = 0; mi < 2; ++mi) {
                rsum[mi][0] += __shfl_xor_sync(0xffffffffu, rsum[mi][0], o);
                rsum[mi][1] += __shfl_xor_sync(0xffffffffu, rsum[mi][1], o);
            }
        }
        __syncthreads();                       // smem stages no longer needed
        float* sp = reinterpret_cast<float*>(smem);   // [2][128]
        if (t4 == 0) {
            const int nwid = wid >> 2;         // 0/1 (n-warp)
            #pragma unroll
            for (int mi = 0; mi < 2; ++mi) {
                sp[nwid * 128 + wm + mi * 16 + g]     = rsum[mi][0];
                sp[nwid * 128 + wm + mi * 16 + g + 8] = rsum[mi][1];
            }
        }
        __syncthreads();
        if (tid < 128) {
            const float s = sp[tid] + sp[128 + tid];
            psum[(long long)(bz * M + m0 + tid) * gridDim.x + blockIdx.x] = s;
        }
        return;
    }

    #pragma unroll
    for (int mi = 0; mi < 2; ++mi) {
        const int row = m0 + wm + mi * 16 + g;
        #pragma unroll
        for (int ni = 0; ni < 8; ++ni) {
            const int col = n0 + wn + ni * 8 + t4 * 2;
            float b0 = 0.0f, b1 = 0.0f;
            if (bias) { b0 = bias[col]; b1 = bias[col + 1]; }
            float v00 = acc[mi][ni][0] + b0, v01 = acc[mi][ni][1] + b1;
            float v10 = acc[mi][ni][2] + b0, v11 = acc[mi][ni][3] + b1;
            if (invS) {
                const float s0 = invS[bz * N + col];
                const float s1 = invS[bz * N + col + 1];
                v00 *= s0; v01 *= s1; v10 *= s0; v11 *= s1;
            }
            if (Cf) {
                float* cg = Cf + bz * sC;
                *reinterpret_cast<float2*>(&cg[(long long)row * N + col])
                    = make_float2(v00, v01);
                *reinterpret_cast<float2*>(&cg[(long long)(row + 8) * N + col])
                    = make_float2(v10, v11);
            }
            if (Ch) {
                uint32_t h, l;
                split2(v00, v01, h, l);
                *reinterpret_cast<uint32_t*>(&Ch[bz * sC + (long long)row * N + col]) = h;
                *reinterpret_cast<uint32_t*>(&Cl[bz * sC + (long long)row * N + col]) = l;
                split2(v10, v11, h, l);
                *reinterpret_cast<uint32_t*>(&Ch[bz * sC + (long long)(row + 8) * N + col]) = h;
                *reinterpret_cast<uint32_t*>(&Cl[bz * sC + (long long)(row + 8) * N + col]) = l;
            }
        }
    }
}

// ---------------------------------------------------------------------------
// Launch
// ---------------------------------------------------------------------------
extern "C" void kernel_launch(void* const* d_in, const int* in_sizes, int n_in,
                              void* d_out, int out_size)
{
    const float* logits   = (const float*)d_in[0];  // [B,L,N]
    const float* features = (const float*)d_in[1];  // [B,N,C]
    const float* Wq       = (const float*)d_in[2];  // [D,C]
    const float* bq       = (const float*)d_in[3];  // [D]
    const float* Wk       = (const float*)d_in[4];  // [D,C]
    const float* bk       = (const float*)d_in[5];  // [D]
    float* out            = (float*)d_out;          // [B,L,N]

    __nv_bfloat16 *feat_h, *feat_l, *log_h, *log_l;
    __nv_bfloat16 *wq_h, *wq_l, *wk_h, *wk_l;
    __nv_bfloat16 *q_h, *q_l, *k_h, *k_l, *attn_h, *attn_l;
    float *psum, *invS;
    cudaGetSymbolAddress((void**)&feat_h, g_feat_h);
    cudaGetSymbolAddress((void**)&feat_l, g_feat_l);
    cudaGetSymbolAddress((void**)&log_h,  g_log_h);
    cudaGetSymbolAddress((void**)&log_l,  g_log_l);
    cudaGetSymbolAddress((void**)&wq_h,   g_wq_h);
    cudaGetSymbolAddress((void**)&wq_l,   g_wq_l);
    cudaGetSymbolAddress((void**)&wk_h,   g_wk_h);
    cudaGetSymbolAddress((void**)&wk_l,   g_wk_l);
    cudaGetSymbolAddress((void**)&q_h,    g_q_h);
    cudaGetSymbolAddress((void**)&q_l,    g_q_l);
    cudaGetSymbolAddress((void**)&k_h,    g_k_h);
    cudaGetSymbolAddress((void**)&k_l,    g_k_l);
    cudaGetSymbolAddress((void**)&attn_h, g_attn_h);
    cudaGetSymbolAddress((void**)&attn_l, g_attn_l);
    cudaGetSymbolAddress((void**)&psum,   g_psum);
    cudaGetSymbolAddress((void**)&invS,   g_invS);

    cudaFuncSetAttribute(hgemm_nt,
                         cudaFuncAttributeMaxDynamicSharedMemorySize, GSMEM);

    // 0) splits
    {
        int n4 = BB * NN * CC / 4;
        split_kernel<<<n4 / 256, 256>>>((const float4*)features,
                                        (uint2*)feat_h, (uint2*)feat_l, n4);
        n4 = BB * LL * NN / 4;
        split_kernel<<<n4 / 256, 256>>>((const float4*)logits,
                                        (uint2*)log_h, (uint2*)log_l, n4);
        n4 = DD * CC / 4;
        split_kernel<<<n4 / 256, 256>>>((const float4*)Wq,
                                        (uint2*)wq_h, (uint2*)wq_l, n4);
        split_kernel<<<n4 / 256, 256>>>((const float4*)Wk,
                                        (uint2*)wk_h, (uint2*)wk_l, n4);
    }

    // 1+2) Projections: [B*N,C] x [D,C]^T -> bf16 hi/lo q,k
    hgemm_nt<<<dim3(1, (BB * NN) / 128, 1), 256, GSMEM>>>(
        feat_h, feat_l, wq_h, wq_l, nullptr, q_h, q_l, bq, nullptr, nullptr,
        BB * NN, DD, CC, 0, 0, 0);
    hgemm_nt<<<dim3(1, (BB * NN) / 128, 1), 256, GSMEM>>>(
        feat_h, feat_l, wk_h, wk_l, nullptr, k_h, k_l, bk, nullptr, nullptr,
        BB * NN, DD, CC, 0, 0, 0);

    // 3) Energy + exp + per-tile row sums (fused; no max needed: |e| <= ~70)
    hgemm_nt<<<dim3(NN / 128, NN / 128, BB), 256, GSMEM>>>(
        q_h, q_l, k_h, k_l, nullptr, attn_h, attn_l, nullptr, psum, nullptr,
        NN, NN, DD,
        (long long)NN * DD, (long long)NN * DD, (long long)NN * NN);

    // 4) Row sums -> 1/S
    rowsum_inv_kernel<<<(BB * NN) / 256, 256>>>(psum, invS, NN / 128);

    // 5) Aggregation with folded normalization:
    //    out[l,m] = (sum_n logits[l,n] * P[m,n]) * invS[m]
    hgemm_nt<<<dim3(NN / 128, LL / 128, BB), 256, GSMEM>>>(
        log_h, log_l, attn_h, attn_l, out, nullptr, nullptr, nullptr,
        nullptr, invS,
        LL, NN, NN,
        (long long)LL * NN, (long long)NN * NN, (long long)LL * NN);
}

// round 7
// speedup vs baseline: 1.4722x; 1.4722x over previous
#include <cuda_runtime.h>
#include <cuda_bf16.h>
#include <math.h>
#include <stdint.h>

// Problem shape constants
#define BB 8
#define LL 512
#define NN 2048
#define CC 1024
#define DD 128

// ---------------------------------------------------------------------------
// Scratch (device globals — no allocations allowed)
// ---------------------------------------------------------------------------
__device__ __align__(16) __nv_bfloat16 g_feat_h[BB * NN * CC];   // 32 MB
__device__ __align__(16) __nv_bfloat16 g_feat_l[BB * NN * CC];
__device__ __align__(16) __nv_bfloat16 g_log_h[BB * LL * NN];    // 16 MB
__device__ __align__(16) __nv_bfloat16 g_log_l[BB * LL * NN];
__device__ __align__(16) __nv_bfloat16 g_wq_h[DD * CC];
__device__ __align__(16) __nv_bfloat16 g_wq_l[DD * CC];
__device__ __align__(16) __nv_bfloat16 g_wk_h[DD * CC];
__device__ __align__(16) __nv_bfloat16 g_wk_l[DD * CC];
__device__ __align__(16) __nv_bfloat16 g_q_h[BB * NN * DD];      // 4 MB
__device__ __align__(16) __nv_bfloat16 g_q_l[BB * NN * DD];
__device__ __align__(16) __nv_bfloat16 g_k_h[BB * NN * DD];
__device__ __align__(16) __nv_bfloat16 g_k_l[BB * NN * DD];
__device__ __align__(16) float g_energy[(size_t)BB * NN * NN];   // 128 MB
__device__ __align__(16) __nv_bfloat16 g_attn_h[(size_t)BB * NN * NN]; // 64 MB
__device__ __align__(16) __nv_bfloat16 g_attn_l[(size_t)BB * NN * NN]; // 64 MB

// ---------------------------------------------------------------------------
// Helpers (family-portable PTX only: ldmatrix / mma.sync / cp.async)
// ---------------------------------------------------------------------------
__device__ __forceinline__ uint32_t smem_u32(const void* p) {
    uint32_t a;
    asm("{ .reg .u64 t; cvta.to.shared.u64 t, %1; cvt.u32.u64 %0, t; }"
        : "=r"(a) : "l"(p));
    return a;
}

__device__ __forceinline__ uint32_t sw128(uint32_t off) {
    return off ^ ((off >> 3) & 0x70);
}

__device__ __forceinline__ void ldm_x4(uint32_t r[4], uint32_t addr) {
    asm volatile("ldmatrix.sync.aligned.m8n8.x4.shared.b16 {%0,%1,%2,%3}, [%4];"
                 : "=r"(r[0]), "=r"(r[1]), "=r"(r[2]), "=r"(r[3])
                 : "r"(addr));
}

__device__ __forceinline__ void mma_bf16(float d[4], const uint32_t a[4],
                                         uint32_t b0, uint32_t b1) {
    asm volatile(
        "mma.sync.aligned.m16n8k16.row.col.f32.bf16.bf16.f32 "
        "{%0,%1,%2,%3}, {%4,%5,%6,%7}, {%8,%9}, {%0,%1,%2,%3};"
        : "+f"(d[0]), "+f"(d[1]), "+f"(d[2]), "+f"(d[3])
        : "r"(a[0]), "r"(a[1]), "r"(a[2]), "r"(a[3]), "r"(b0), "r"(b1));
}

__device__ __forceinline__ void cpa16(uint32_t dst, const void* src) {
    asm volatile("cp.async.cg.shared.global [%0], [%1], 16;"
                 :: "r"(dst), "l"(src));
}
__device__ __forceinline__ void cp_commit() {
    asm volatile("cp.async.commit_group;" ::: "memory");
}
__device__ __forceinline__ void cp_wait1() {
    asm volatile("cp.async.wait_group 1;" ::: "memory");
}
__device__ __forceinline__ void cp_wait0() {
    asm volatile("cp.async.wait_group 0;" ::: "memory");
}

// Fast split fp32 -> (bf16 hi, bf16 lo) packed pairs.
// hi = round-toward-zero truncation (PRMT), lo = rn(residual) packed cvt.
// All fixed-latency ALU ops, no F2FP chains.
__device__ __forceinline__ void split2(float x0, float x1, uint32_t& hi, uint32_t& lo) {
    const uint32_t xi0 = __float_as_uint(x0);
    const uint32_t xi1 = __float_as_uint(x1);
    asm("prmt.b32 %0, %1, %2, 0x7632;" : "=r"(hi) : "r"(xi0), "r"(xi1));
    const float t0 = __uint_as_float(xi0 & 0xFFFF0000u);
    const float t1 = __uint_as_float(xi1 & 0xFFFF0000u);
    const float l0 = x0 - t0;
    const float l1 = x1 - t1;
    asm("cvt.rn.bf16x2.f32 %0, %1, %2;" : "=r"(lo) : "f"(l1), "f"(l0));
}

// ---------------------------------------------------------------------------
// Merged elementwise split for all 4 input tensors: fp32 -> hi/lo bf16
// ---------------------------------------------------------------------------
#define F4C (BB * NN * CC / 4)
#define L4C (BB * LL * NN / 4)
#define W4C (DD * CC / 4)

__global__ __launch_bounds__(256) void split_all_kernel(
    const float4* __restrict__ feat, const float4* __restrict__ logi,
    const float4* __restrict__ wq,   const float4* __restrict__ wk,
    uint2* __restrict__ fh, uint2* __restrict__ fl,
    uint2* __restrict__ lh, uint2* __restrict__ ll,
    uint2* __restrict__ qh, uint2* __restrict__ ql,
    uint2* __restrict__ kh, uint2* __restrict__ kl)
{
    const int i = blockIdx.x * 256 + threadIdx.x;
    const float4* src;
    uint2 *ho, *lo_;
    int j;
    if (i < F4C)                    { src = feat; j = i;                   ho = fh; lo_ = fl; }
    else if (i < F4C + L4C)         { src = logi; j = i - F4C;             ho = lh; lo_ = ll; }
    else if (i < F4C + L4C + W4C)   { src = wq;   j = i - F4C - L4C;       ho = qh; lo_ = ql; }
    else                            { src = wk;   j = i - F4C - L4C - W4C; ho = kh; lo_ = kl; }

    float4 v = src[j];
    uint32_t h0, l0, h1, l1;
    split2(v.x, v.y, h0, l0);
    split2(v.z, v.w, h1, l1);
    ho[j]  = make_uint2(h0, h1);
    lo_[j] = make_uint2(l0, l1);
}

// ---------------------------------------------------------------------------
// bf16 HMMA NT GEMM with 3-term split: C = Ah*Bh + Al*Bh + Ah*Bl
// A tiles [M,K] bf16 row-major (hi+lo), B tiles [N,K] bf16 row-major (hi+lo).
// CTA tile 128x128, K-chunk 64, 3-stage cp.async pipeline.
// Output: fp32 (Cf) and/or bf16 hi/lo (Ch/Cl), + optional bias.
// ---------------------------------------------------------------------------
#define NSTAGE 3
#define STAGE_BYTES 65536   // Ah 16K | Al 16K | Bh 16K | Bl 16K
#define GSMEM (NSTAGE * STAGE_BYTES)

__device__ __forceinline__ void fill_stage(uint32_t st,
    const __nv_bfloat16* __restrict__ ah, const __nv_bfloat16* __restrict__ al,
    const __nv_bfloat16* __restrict__ bh, const __nv_bfloat16* __restrict__ bl,
    int K, int tid)
{
    #pragma unroll
    for (int i = 0; i < 4; ++i) {
        const int id  = tid + (i << 8);
        const int row = id >> 3, g = id & 7;
        const long long goff = (long long)row * K + (g << 3);
        const uint32_t so = sw128((uint32_t)((row << 7) + (g << 4)));
        cpa16(st + so,          ah + goff);
        cpa16(st + 16384 + so,  al + goff);
        cpa16(st + 32768 + so,  bh + goff);
        cpa16(st + 49152 + so,  bl + goff);
    }
    cp_commit();
}

__global__ __launch_bounds__(256, 1) void hgemm_nt(
    const __nv_bfloat16* __restrict__ Ah, const __nv_bfloat16* __restrict__ Al,
    const __nv_bfloat16* __restrict__ Bh, const __nv_bfloat16* __restrict__ Bl,
    float* __restrict__ Cf,
    __nv_bfloat16* __restrict__ Ch, __nv_bfloat16* __restrict__ Cl,
    const float* __restrict__ bias,
    int M, int N, int K,
    long long sA, long long sB, long long sC)
{
    extern __shared__ char smem[];
    const uint32_t sbase = smem_u32(smem);
    const int tid  = threadIdx.x;
    const int lane = tid & 31;
    const int wid  = tid >> 5;

    const int bz = blockIdx.z;
    const int m0 = blockIdx.y * 128;
    const int n0 = blockIdx.x * 128;

    const __nv_bfloat16* Aht = Ah + bz * sA + (long long)m0 * K;
    const __nv_bfloat16* Alt = Al + bz * sA + (long long)m0 * K;
    const __nv_bfloat16* Bht = Bh + bz * sB + (long long)n0 * K;
    const __nv_bfloat16* Blt = Bl + bz * sB + (long long)n0 * K;

    // warp tiling: 8 warps = 4(m) x 2(n); warp tile 32(m) x 64(n)
    const int wm = (wid & 3) * 32;
    const int wn = (wid >> 2) * 64;
    const int qq = lane >> 3;
    const int rr = lane & 7;

    float acc[2][8][4];
    #pragma unroll
    for (int mi = 0; mi < 2; mi++)
        #pragma unroll
        for (int ni = 0; ni < 8; ni++)
            #pragma unroll
            for (int c = 0; c < 4; c++) acc[mi][ni][c] = 0.0f;

    const int nch = K / 64;

    fill_stage(sbase, Aht, Alt, Bht, Blt, K, tid);
    if (nch > 1)
        fill_stage(sbase + STAGE_BYTES, Aht + 64, Alt + 64, Bht + 64, Blt + 64, K, tid);

    for (int it = 0; it < nch; ++it) {
        if (it + 1 < nch) cp_wait1(); else cp_wait0();
        __syncthreads();

        const uint32_t st = sbase + (uint32_t)(it % NSTAGE) * STAGE_BYTES;

        #pragma unroll
        for (int ks = 0; ks < 4; ++ks) {
            const int ko = ks * 16;
            uint32_t ah[2][4], al[2][4], bb[4][4];
            uint32_t aoff[2], boff[4];
            #pragma unroll
            for (int mi = 0; mi < 2; ++mi) {
                aoff[mi] = sw128((uint32_t)((wm + mi * 16 + rr + (qq & 1) * 8) * 128
                                            + (ko + (qq >> 1) * 8) * 2));
                ldm_x4(ah[mi], st + aoff[mi]);
                ldm_x4(al[mi], st + 16384 + aoff[mi]);
            }
            #pragma unroll
            for (int bi = 0; bi < 4; ++bi) {
                boff[bi] = sw128((uint32_t)((wn + bi * 16 + rr + (qq >> 1) * 8) * 128
                                            + (ko + (qq & 1) * 8) * 2));
                ldm_x4(bb[bi], st + 32768 + boff[bi]);
            }
            // hi*hi
            #pragma unroll
            for (int mi = 0; mi < 2; ++mi)
                #pragma unroll
                for (int ni = 0; ni < 8; ++ni)
                    mma_bf16(acc[mi][ni], ah[mi],
                             bb[ni >> 1][(ni & 1) * 2], bb[ni >> 1][(ni & 1) * 2 + 1]);
            // lo*hi
            #pragma unroll
            for (int mi = 0; mi < 2; ++mi)
                #pragma unroll
                for (int ni = 0; ni < 8; ++ni)
                    mma_bf16(acc[mi][ni], al[mi],
                             bb[ni >> 1][(ni & 1) * 2], bb[ni >> 1][(ni & 1) * 2 + 1]);
            // hi*lo (reload bb with B_lo)
            #pragma unroll
            for (int bi = 0; bi < 4; ++bi)
                ldm_x4(bb[bi], st + 49152 + boff[bi]);
            #pragma unroll
            for (int mi = 0; mi < 2; ++mi)
                #pragma unroll
                for (int ni = 0; ni < 8; ++ni)
                    mma_bf16(acc[mi][ni], ah[mi],
                             bb[ni >> 1][(ni & 1) * 2], bb[ni >> 1][(ni & 1) * 2 + 1]);
        }

        if (it + 2 < nch) {
            const int k0 = (it + 2) * 64;
            fill_stage(sbase + (uint32_t)((it + 2) % NSTAGE) * STAGE_BYTES,
                       Aht + k0, Alt + k0, Bht + k0, Blt + k0, K, tid);
        }
    }

    // epilogue
    const int g  = lane >> 2;
    const int t4 = lane & 3;
    #pragma unroll
    for (int mi = 0; mi < 2; ++mi) {
        const int row = m0 + wm + mi * 16 + g;
        #pragma unroll
        for (int ni = 0; ni < 8; ++ni) {
            const int col = n0 + wn + ni * 8 + t4 * 2;
            float b0 = 0.0f, b1 = 0.0f;
            if (bias) { b0 = bias[col]; b1 = bias[col + 1]; }
            const float v00 = acc[mi][ni][0] + b0, v01 = acc[mi][ni][1] + b1;
            const float v10 = acc[mi][ni][2] + b0, v11 = acc[mi][ni][3] + b1;
            if (Cf) {
                float* cg = Cf + bz * sC;
                *reinterpret_cast<float2*>(&cg[(long long)row * N + col])
                    = make_float2(v00, v01);
                *reinterpret_cast<float2*>(&cg[(long long)(row + 8) * N + col])
                    = make_float2(v10, v11);
            }
            if (Ch) {
                uint32_t h, l;
                split2(v00, v01, h, l);
                *reinterpret_cast<uint32_t*>(&Ch[bz * sC + (long long)row * N + col]) = h;
                *reinterpret_cast<uint32_t*>(&Cl[bz * sC + (long long)row * N + col]) = l;
                split2(v10, v11, h, l);
                *reinterpret_cast<uint32_t*>(&Ch[bz * sC + (long long)(row + 8) * N + col]) = h;
                *reinterpret_cast<uint32_t*>(&Cl[bz * sC + (long long)(row + 8) * N + col]) = l;
            }
        }
    }
}

// ---------------------------------------------------------------------------
// Single-pass row softmax WITHOUT max subtraction (|energy| <= ~70, exp safe
// in fp32). Row length 2048, 256 threads, 8 floats in regs.
// Reads fp32 energy, writes hi/lo bf16 normalized attention.
// ---------------------------------------------------------------------------
__global__ __launch_bounds__(256) void softmax_split_kernel(
    const float* __restrict__ en,
    __nv_bfloat16* __restrict__ hi, __nv_bfloat16* __restrict__ lo)
{
    const size_t base = (size_t)blockIdx.x * NN;
    const int tid = threadIdx.x;
    const float4* src = reinterpret_cast<const float4*>(en + base);
    __shared__ float red[8];

    float4 v0 = src[tid];
    float4 v1 = src[tid + 256];

    v0.x = __expf(v0.x); v0.y = __expf(v0.y);
    v0.z = __expf(v0.z); v0.w = __expf(v0.w);
    v1.x = __expf(v1.x); v1.y = __expf(v1.y);
    v1.z = __expf(v1.z); v1.w = __expf(v1.w);

    float s = v0.x + v0.y + v0.z + v0.w + v1.x + v1.y + v1.z + v1.w;
    #pragma unroll
    for (int o = 16; o; o >>= 1) s += __shfl_xor_sync(0xffffffffu, s, o);
    if ((tid & 31) == 0) red[tid >> 5] = s;
    __syncthreads();
    s = red[0];
    #pragma unroll
    for (int w = 1; w < 8; ++w) s += red[w];
    const float inv = 1.0f / s;

    uint2* ph = reinterpret_cast<uint2*>(hi + base);
    uint2* pl = reinterpret_cast<uint2*>(lo + base);
    uint32_t h0, l0, h1, l1;
    split2(v0.x * inv, v0.y * inv, h0, l0);
    split2(v0.z * inv, v0.w * inv, h1, l1);
    ph[tid] = make_uint2(h0, h1);
    pl[tid] = make_uint2(l0, l1);
    split2(v1.x * inv, v1.y * inv, h0, l0);
    split2(v1.z * inv, v1.w * inv, h1, l1);
    ph[tid + 256] = make_uint2(h0, h1);
    pl[tid + 256] = make_uint2(l0, l1);
}

// ---------------------------------------------------------------------------
// Launch
// ---------------------------------------------------------------------------
extern "C" void kernel_launch(void* const* d_in, const int* in_sizes, int n_in,
                              void* d_out, int out_size)
{
    const float* logits   = (const float*)d_in[0];  // [B,L,N]
    const float* features = (const float*)d_in[1];  // [B,N,C]
    const float* Wq       = (const float*)d_in[2];  // [D,C]
    const float* bq       = (const float*)d_in[3];  // [D]
    const float* Wk       = (const float*)d_in[4];  // [D,C]
    const float* bk       = (const float*)d_in[5];  // [D]
    float* out            = (float*)d_out;          // [B,L,N]

    __nv_bfloat16 *feat_h, *feat_l, *log_h, *log_l;
    __nv_bfloat16 *wq_h, *wq_l, *wk_h, *wk_l;
    __nv_bfloat16 *q_h, *q_l, *k_h, *k_l, *attn_h, *attn_l;
    float* energy;
    cudaGetSymbolAddress((void**)&feat_h, g_feat_h);
    cudaGetSymbolAddress((void**)&feat_l, g_feat_l);
    cudaGetSymbolAddress((void**)&log_h,  g_log_h);
    cudaGetSymbolAddress((void**)&log_l,  g_log_l);
    cudaGetSymbolAddress((void**)&wq_h,   g_wq_h);
    cudaGetSymbolAddress((void**)&wq_l,   g_wq_l);
    cudaGetSymbolAddress((void**)&wk_h,   g_wk_h);
    cudaGetSymbolAddress((void**)&wk_l,   g_wk_l);
    cudaGetSymbolAddress((void**)&q_h,    g_q_h);
    cudaGetSymbolAddress((void**)&q_l,    g_q_l);
    cudaGetSymbolAddress((void**)&k_h,    g_k_h);
    cudaGetSymbolAddress((void**)&k_l,    g_k_l);
    cudaGetSymbolAddress((void**)&attn_h, g_attn_h);
    cudaGetSymbolAddress((void**)&attn_l, g_attn_l);
    cudaGetSymbolAddress((void**)&energy, g_energy);

    cudaFuncSetAttribute(hgemm_nt,
                         cudaFuncAttributeMaxDynamicSharedMemorySize, GSMEM);

    // 0) one merged split pass over all four inputs
    {
        const int total4 = F4C + L4C + 2 * W4C;
        split_all_kernel<<<(total4 + 255) / 256, 256>>>(
            (const float4*)features, (const float4*)logits,
            (const float4*)Wq, (const float4*)Wk,
            (uint2*)feat_h, (uint2*)feat_l,
            (uint2*)log_h,  (uint2*)log_l,
            (uint2*)wq_h,   (uint2*)wq_l,
            (uint2*)wk_h,   (uint2*)wk_l);
    }

    // 1+2) Projections: [B*N,C] x [D,C]^T -> bf16 hi/lo q,k
    hgemm_nt<<<dim3(1, (BB * NN) / 128, 1), 256, GSMEM>>>(
        feat_h, feat_l, wq_h, wq_l, nullptr, q_h, q_l, bq,
        BB * NN, DD, CC, 0, 0, 0);
    hgemm_nt<<<dim3(1, (BB * NN) / 128, 1), 256, GSMEM>>>(
        feat_h, feat_l, wk_h, wk_l, nullptr, k_h, k_l, bk,
        BB * NN, DD, CC, 0, 0, 0);

    // 3) Energy: per batch Q[2048,128] @ K^T -> fp32
    hgemm_nt<<<dim3(NN / 128, NN / 128, BB), 256, GSMEM>>>(
        q_h, q_l, k_h, k_l, energy, nullptr, nullptr, nullptr,
        NN, NN, DD,
        (long long)NN * DD, (long long)NN * DD, (long long)NN * NN);

    // 4) Softmax (single pass, no max) -> attn hi/lo bf16
    softmax_split_kernel<<<BB * NN, 256>>>(energy, attn_h, attn_l);

    // 5) Aggregation: out[b,l,m] = sum_n logits[b,l,n]*attn[b,m,n]
    hgemm_nt<<<dim3(NN / 128, LL / 128, BB), 256, GSMEM>>>(
        log_h, log_l, attn_h, attn_l, out, nullptr, nullptr, nullptr,
        LL, NN, NN,
        (long long)LL * NN, (long long)NN * NN, (long long)LL * NN);
}